// round 16
// baseline (speedup 1.0000x reference)
#include <cuda_runtime.h>
#include <math.h>
#include <stdint.h>

#define NSRC   2048
#define NGRID  50000
#define NLOCS  500
#define KTOP   5
#define NSLICE 256
#define SL     196          // ceil(50000/256); last slice has 20 points
#define NPAIR  98           // SL/2
#define SPT    4            // sources per thread in slice_min
#define SMT    128          // threads in slice_min
#define FINF   __int_as_float(0x7f800000)
#define IBIG   0x7fffffff

// ---------------- device scratch ----------------
__device__ float g_sd[NSRC * NSLICE];      // per (src, slice) min "e"

// ---------------- f32x2 packed helpers (sm_103a FFMA2) ----------------
__device__ __forceinline__ unsigned long long pk2(float lo, float hi) {
    unsigned long long r;
    asm("mov.b64 %0, {%1, %2};"
        : "=l"(r) : "r"(__float_as_uint(lo)), "r"(__float_as_uint(hi)));
    return r;
}
__device__ __forceinline__ unsigned long long fma2(unsigned long long a,
                                                   unsigned long long b,
                                                   unsigned long long c) {
    unsigned long long d;
    asm("fma.rn.f32x2 %0, %1, %2, %3;" : "=l"(d) : "l"(a), "l"(b), "l"(c));
    return d;
}
__device__ __forceinline__ void upk2(unsigned long long v, float& lo, float& hi) {
    unsigned int a, b;
    asm("mov.b64 {%0, %1}, %2;" : "=r"(a), "=r"(b) : "l"(v));
    lo = __uint_as_float(a);
    hi = __uint_as_float(b);
}
__device__ __forceinline__ float fsqrt_approx(float x) {
    float r;
    asm("sqrt.approx.f32 %0, %1;" : "=f"(r) : "f"(x));
    return r;
}

// lexicographic (value, index): lower value wins; tie -> lower index
__device__ __forceinline__ bool lexless(float a, int ai, float b, int bi) {
    return (a < b) || (a == b && ai < bi);
}

// ============ kernel 1: per-(src, slice) branchless minimum ============
// (R15, at its measured floor ~20 us) grid = (4, 256); 128 threads; SPT=4.
// Ordering key: e = |g|^2 - 2*s.g  (== d2 - |s|^2, same order as ref d2).
__global__ __launch_bounds__(SMT)
void slice_min_kernel(const float* __restrict__ src,
                      const float* __restrict__ grid) {
    __shared__ ulonglong2 tileA[NPAIR];   // (xx = x0|x1, yy = y0|y1)
    __shared__ ulonglong2 tileB[NPAIR];   // (zz = z0|z1, ww = w0|w1)

    const int slice = blockIdx.y;
    const int base  = slice * SL;
    const int n     = min(SL, NGRID - base);      // 196 or 20
    const int npair = (n + 1) >> 1;

    if (threadIdx.x < npair) {
        const int p  = threadIdx.x;
        const int g0 = base + 2 * p;
        const int g1 = g0 + 1;
        float x0 = grid[g0 * 3 + 0] / 1000.0f;
        float y0 = grid[g0 * 3 + 1] / 1000.0f;
        float z0 = grid[g0 * 3 + 2] / 1000.0f;
        float w0 = __fadd_rn(__fadd_rn(__fmul_rn(x0, x0), __fmul_rn(y0, y0)),
                             __fmul_rn(z0, z0));
        float x1 = 1e30f, y1 = 1e30f, z1 = 1e30f, w1 = 1e30f;  // pad -> huge e
        if (2 * p + 1 < n) {
            x1 = grid[g1 * 3 + 0] / 1000.0f;
            y1 = grid[g1 * 3 + 1] / 1000.0f;
            z1 = grid[g1 * 3 + 2] / 1000.0f;
            w1 = __fadd_rn(__fadd_rn(__fmul_rn(x1, x1), __fmul_rn(y1, y1)),
                           __fmul_rn(z1, z1));
        }
        ulonglong2 a, b;
        a.x = pk2(x0, x1); a.y = pk2(y0, y1);
        b.x = pk2(z0, z1); b.y = pk2(w0, w1);
        tileA[p] = a;
        tileB[p] = b;
    }
    __syncthreads();

    const int s0 = blockIdx.x * (SMT * SPT) + threadIdx.x;

    unsigned long long mx2[SPT], my2[SPT], mz2[SPT];
#pragma unroll
    for (int k = 0; k < SPT; k++) {
        const int s = s0 + k * SMT;
        float mx = -2.0f * (src[s * 3 + 0] / 1000.0f);
        float my = -2.0f * (src[s * 3 + 1] / 1000.0f);
        float mz = -2.0f * (src[s * 3 + 2] / 1000.0f);
        mx2[k] = pk2(mx, mx);
        my2[k] = pk2(my, my);
        mz2[k] = pk2(mz, mz);
    }

    float accL[SPT], accH[SPT];
#pragma unroll
    for (int k = 0; k < SPT; k++) { accL[k] = FINF; accH[k] = FINF; }

#pragma unroll 7
    for (int p = 0; p < npair; p++) {
        const ulonglong2 A = tileA[p];   // A.x = xx, A.y = yy
        const ulonglong2 B = tileB[p];   // B.x = zz, B.y = ww
#pragma unroll
        for (int k = 0; k < SPT; k++) {
            unsigned long long e = fma2(mz2[k], B.x, B.y);
            e = fma2(my2[k], A.y, e);
            e = fma2(mx2[k], A.x, e);
            float lo, hi;
            upk2(e, lo, hi);
            accL[k] = fminf(accL[k], lo);
            accH[k] = fminf(accH[k], hi);
        }
    }

#pragma unroll
    for (int k = 0; k < SPT; k++) {
        const int s = s0 + k * SMT;
        g_sd[s * NSLICE + slice] = fminf(accL[k], accH[k]);
    }
}

// ============ kernel 2: fused select + bias mean + epilogue ============
// 1024 blocks x 512 threads; block = 2 sources, each handled by a
// 256-thread half running the proven R14 3-barrier select, then a
// block-wide bias stream + epilogue.
__global__ __launch_bounds__(512)
void tail_kernel(const float* __restrict__ src,
                 const int*   __restrict__ ind,
                 const float* __restrict__ log_amp,
                 const int*   __restrict__ phase,
                 const float* __restrict__ locs,
                 const float* __restrict__ mag_coef,
                 const float* __restrict__ eps_coef,
                 const float* __restrict__ dep_coef,
                 const float* __restrict__ bias,
                 const float* __restrict__ grid,
                 float*       __restrict__ out) {
    const int s0   = blockIdx.x * 2;
    const int tid  = threadIdx.x;
    const int half = tid >> 8;          // 0 or 1 -> source s0+half
    const int t    = tid & 255;
    const int lane = t & 31;
    const int wid8 = t >> 5;            // warp id within the half (0..7)
    const int s    = s0 + half;

    __shared__ float swv[2][8 * KTOP];
    __shared__ int   swj[2][8 * KTOP];
    __shared__ int   csl[2][KTOP];
    __shared__ int   tks[2][KTOP];
    __shared__ float bsum[2][NLOCS];

    // ---- stage A: per-warp top-5 of slice minima ----
    {
        float v = g_sd[s * NSLICE + t];
        int   j = t;
#pragma unroll
        for (int r = 0; r < KTOP; r++) {
            float bv = v; int bi = j;
#pragma unroll
            for (int off = 16; off > 0; off >>= 1) {
                float ov = __shfl_xor_sync(0xffffffffu, bv, off);
                int   oi = __shfl_xor_sync(0xffffffffu, bi, off);
                if (lexless(ov, oi, bv, bi)) { bv = ov; bi = oi; }
            }
            if (lane == 0) { swv[half][wid8 * KTOP + r] = bv;
                             swj[half][wid8 * KTOP + r] = bi; }
            if (v == bv && j == bi) { v = FINF; j = IBIG; }  // ids unique
        }
    }
    __syncthreads();

    // ---- warp 0 of each half: merge 8 sorted 5-lists -> csl ----
    if (wid8 == 0) {
        float h0 = FINF, h1 = FINF, h2 = FINF, h3 = FINF, h4 = FINF;
        int   g0 = IBIG, g1 = IBIG, g2 = IBIG, g3 = IBIG, g4 = IBIG;
        if (lane < 8) {
            h0 = swv[half][lane * KTOP + 0]; g0 = swj[half][lane * KTOP + 0];
            h1 = swv[half][lane * KTOP + 1]; g1 = swj[half][lane * KTOP + 1];
            h2 = swv[half][lane * KTOP + 2]; g2 = swj[half][lane * KTOP + 2];
            h3 = swv[half][lane * KTOP + 3]; g3 = swj[half][lane * KTOP + 3];
            h4 = swv[half][lane * KTOP + 4]; g4 = swj[half][lane * KTOP + 4];
        }
#pragma unroll
        for (int r = 0; r < KTOP; r++) {
            float bv = h0; int bi = g0;
#pragma unroll
            for (int off = 16; off > 0; off >>= 1) {
                float ov = __shfl_xor_sync(0xffffffffu, bv, off);
                int   oi = __shfl_xor_sync(0xffffffffu, bi, off);
                if (lexless(ov, oi, bv, bi)) { bv = ov; bi = oi; }
            }
            if (lane == 0) csl[half][r] = bi;
            if (h0 == bv && g0 == bi) {
                h0 = h1; g0 = g1; h1 = h2; g1 = g2;
                h2 = h3; g2 = g3; h3 = h4; g3 = g4;
                h4 = FINF; g4 = IBIG;
            }
        }
    }
    __syncthreads();

    // ---- stage B/C: rescan <=980 candidates, lane sort-4, warp merge ----
    const float mx = -2.0f * (src[s * 3 + 0] / 1000.0f);
    const float my = -2.0f * (src[s * 3 + 1] / 1000.0f);
    const float mz = -2.0f * (src[s * 3 + 2] / 1000.0f);

    float cv[4];
    int   cg[4];
#pragma unroll
    for (int i = 0; i < 4; i++) {
        const int p = t + 256 * i;
        float e = FINF;
        int   gidx = IBIG;
        if (p < KTOP * SL) {
            const int k  = p / SL;
            const int jj = p - k * SL;
            const int gi = csl[half][k] * SL + jj;
            if (gi < NGRID) {
                float x = grid[gi * 3 + 0] / 1000.0f;
                float y = grid[gi * 3 + 1] / 1000.0f;
                float z = grid[gi * 3 + 2] / 1000.0f;
                float n2 = __fadd_rn(__fadd_rn(__fmul_rn(x, x),
                                               __fmul_rn(y, y)),
                                     __fmul_rn(z, z));
                e = fmaf(mx, x, fmaf(my, y, fmaf(mz, z, n2)));
                gidx = gi;
            }
        }
        cv[i] = e;
        cg[i] = gidx;
    }

    // branchless sort-4 ascending by (e, gidx)
#define CE(a, b) { bool sw = lexless(cv[b], cg[b], cv[a], cg[a]);            \
                   float tv = sw ? cv[b] : cv[a]; float uv = sw ? cv[a] : cv[b]; \
                   int   tg = sw ? cg[b] : cg[a]; int   ug = sw ? cg[a] : cg[b]; \
                   cv[a] = tv; cv[b] = uv; cg[a] = tg; cg[b] = ug; }
    CE(0, 1) CE(2, 3) CE(0, 2) CE(1, 3) CE(1, 2)
#undef CE

    // warp merge: top-5 over 32 sorted 4-lists
#pragma unroll
    for (int r = 0; r < KTOP; r++) {
        float bv = cv[0]; int bi = cg[0];
#pragma unroll
        for (int off = 16; off > 0; off >>= 1) {
            float ov = __shfl_xor_sync(0xffffffffu, bv, off);
            int   oi = __shfl_xor_sync(0xffffffffu, bi, off);
            if (lexless(ov, oi, bv, bi)) { bv = ov; bi = oi; }
        }
        if (lane == 0) { swv[half][wid8 * KTOP + r] = bv;
                         swj[half][wid8 * KTOP + r] = bi; }
        if (cv[0] == bv && cg[0] == bi) {   // real ids unique; INF pads benign
            cv[0] = cv[1]; cg[0] = cg[1]; cv[1] = cv[2]; cg[1] = cg[2];
            cv[2] = cv[3]; cg[2] = cg[3]; cv[3] = FINF; cg[3] = IBIG;
        }
    }
    __syncthreads();

    // ---- warp 0 of each half: merge 8 sorted 5-lists -> tks ----
    if (wid8 == 0) {
        float h0 = FINF, h1 = FINF, h2 = FINF, h3 = FINF, h4 = FINF;
        int   g0 = IBIG, g1 = IBIG, g2 = IBIG, g3 = IBIG, g4 = IBIG;
        if (lane < 8) {
            h0 = swv[half][lane * KTOP + 0]; g0 = swj[half][lane * KTOP + 0];
            h1 = swv[half][lane * KTOP + 1]; g1 = swj[half][lane * KTOP + 1];
            h2 = swv[half][lane * KTOP + 2]; g2 = swj[half][lane * KTOP + 2];
            h3 = swv[half][lane * KTOP + 3]; g3 = swj[half][lane * KTOP + 3];
            h4 = swv[half][lane * KTOP + 4]; g4 = swj[half][lane * KTOP + 4];
        }
#pragma unroll
        for (int r = 0; r < KTOP; r++) {
            float bv = h0; int bi = g0;
#pragma unroll
            for (int off = 16; off > 0; off >>= 1) {
                float ov = __shfl_xor_sync(0xffffffffu, bv, off);
                int   oi = __shfl_xor_sync(0xffffffffu, bi, off);
                if (lexless(ov, oi, bv, bi)) { bv = ov; bi = oi; }
            }
            if (lane == 0) tks[half][r] = bi;
            if (h0 == bv && g0 == bi) {
                h0 = h1; g0 = g1; h1 = h2; g1 = g2;
                h2 = h3; g2 = g3; h3 = h4; g3 = g4;
                h4 = FINF; g4 = IBIG;
            }
        }
    }
    __syncthreads();

    const int ph = phase[0];

    // ---- bias means for 2 sources (coalesced 8B-stride row streams) ----
    for (int task = tid; task < 2 * NLOCS; task += 512) {
        const int ss = task / NLOCS;
        const int j  = task - ss * NLOCS;
        const int col = j * 2 + ph;
        float acc = __ldg(&bias[(size_t)tks[ss][0] * (NLOCS * 2) + col]);
        acc += __ldg(&bias[(size_t)tks[ss][1] * (NLOCS * 2) + col]);
        acc += __ldg(&bias[(size_t)tks[ss][2] * (NLOCS * 2) + col]);
        acc += __ldg(&bias[(size_t)tks[ss][3] * (NLOCS * 2) + col]);
        acc += __ldg(&bias[(size_t)tks[ss][4] * (NLOCS * 2) + col]);
        bsum[ss][j] = acc / 5.0f;
    }
    __syncthreads();

    // ---- epilogue: 2 outputs per thread ----
    if (tid >= NLOCS) return;

    const float ec    = eps_coef[ph];
    const float dc    = dep_coef[ph];
    const float denom = fmaxf(mag_coef[ph], 1e-12f);

    const int li = ind[tid];
    const float lx = locs[li * 3 + 0];
    const float ly = locs[li * 3 + 1];
    const float lz = locs[li * 3 + 2];

#pragma unroll
    for (int ss = 0; ss < 2; ss++) {
        const int sq = s0 + ss;
        const float sx = src[sq * 3 + 0];
        const float sy = src[sq * 3 + 1];
        const float sz = src[sq * 3 + 2];

        const float dx = sx - lx;
        const float dy = sy - ly;
        const float d0  = fsqrt_approx(__fadd_rn(__fmul_rn(dx, dx),
                                                 __fmul_rn(dy, dy)));
        const float ld0 = __log10f(d0 + 1.0f);
        const float ldd = __log10f(fabsf(sz - lz) + 1.0f);

        const float b  = bsum[ss][li];
        const float la = log_amp[sq * NLOCS + tid];
        out[sq * NLOCS + tid] = (la - ec * ld0 - dc * ldd - b) / denom;
    }
}

// ---------------- launch ----------------
extern "C" void kernel_launch(void* const* d_in, const int* in_sizes, int n_in,
                              void* d_out, int out_size) {
    const float* src      = (const float*)d_in[0];
    const int*   ind      = (const int*)  d_in[1];
    const float* log_amp  = (const float*)d_in[2];
    const int*   phase    = (const int*)  d_in[3];
    const float* locs     = (const float*)d_in[4];
    const float* grid     = (const float*)d_in[5];
    const float* mag_coef = (const float*)d_in[6];
    const float* eps_coef = (const float*)d_in[7];
    const float* dep_coef = (const float*)d_in[8];
    const float* bias     = (const float*)d_in[9];
    float* out = (float*)d_out;

    dim3 g1(NSRC / (SMT * SPT), NSLICE);
    slice_min_kernel<<<g1, SMT>>>(src, grid);

    tail_kernel<<<NSRC / 2, 512>>>(src, ind, log_amp, phase, locs,
                                   mag_coef, eps_coef, dep_coef, bias,
                                   grid, out);
}